// round 2
// baseline (speedup 1.0000x reference)
#include <cuda_runtime.h>
#include <math.h>

// Scratch state (no cudaMalloc allowed anywhere).
__device__ double g_cos_sum;
__device__ int    g_is64;

// Detect label dtype on device + zero the accumulator.
// If the buffer really is int64 (values < C), every high 32-bit word of the
// first 32 entries is 0 and every low word is in [0, C). If it is int32,
// the "high words" are random labels -> detection flips to int32.
__global__ void init_kernel(const void* labels_raw, int B, int C) {
    const long long* l64 = (const long long*)labels_raw;
    int n = (B < 32) ? B : 32;
    bool ok64 = true;
    for (int i = 0; i < n; i++) {
        long long v = l64[i];
        if (v < 0 || v >= (long long)C) { ok64 = false; break; }
    }
    g_is64 = ok64 ? 1 : 0;
    g_cos_sum = 0.0;
}

// One warp per sample, D == 512 fast path: 4 float4 per lane per tensor.
__global__ __launch_bounds__(256) void cos_kernel_d512(
    const float* __restrict__ emb,
    const void*  __restrict__ labels_raw,
    const float* __restrict__ protos,
    int B, int C)
{
    const int warps_per_block = blockDim.x >> 5;
    const int warp = blockIdx.x * warps_per_block + (threadIdx.x >> 5);
    const int lane = threadIdx.x & 31;

    float dep = 0.f, dee = 0.f, dpp = 0.f;

    if (warp < B) {
        long long lab;
        if (g_is64) lab = ((const long long*)labels_raw)[warp];
        else        lab = (long long)((const int*)labels_raw)[warp];
        if (lab < 0) lab = 0;
        if (lab >= (long long)C) lab = C - 1;   // safety clamp (no crash path)

        const float4* e = reinterpret_cast<const float4*>(emb + (size_t)warp * 512);
        const float4* p = reinterpret_cast<const float4*>(protos + (size_t)lab * 512);

        #pragma unroll
        for (int k = 0; k < 4; k++) {
            float4 ev = e[lane + 32 * k];
            float4 pv = p[lane + 32 * k];
            dep = fmaf(ev.x, pv.x, fmaf(ev.y, pv.y, fmaf(ev.z, pv.z, fmaf(ev.w, pv.w, dep))));
            dee = fmaf(ev.x, ev.x, fmaf(ev.y, ev.y, fmaf(ev.z, ev.z, fmaf(ev.w, ev.w, dee))));
            dpp = fmaf(pv.x, pv.x, fmaf(pv.y, pv.y, fmaf(pv.z, pv.z, fmaf(pv.w, pv.w, dpp))));
        }
    }

    #pragma unroll
    for (int off = 16; off > 0; off >>= 1) {
        dep += __shfl_xor_sync(0xFFFFFFFFu, dep, off);
        dee += __shfl_xor_sync(0xFFFFFFFFu, dee, off);
        dpp += __shfl_xor_sync(0xFFFFFFFFu, dpp, off);
    }

    __shared__ float s_cos[8];
    if (lane == 0) {
        float cosv = 0.f;
        if (warp < B) {
            float en = fmaxf(sqrtf(dee), 1e-8f);
            float pn = fmaxf(sqrtf(dpp), 1e-8f);
            cosv = dep / (en * pn);
        }
        s_cos[threadIdx.x >> 5] = cosv;
    }
    __syncthreads();

    if (threadIdx.x == 0) {
        float acc = 0.f;
        #pragma unroll
        for (int w = 0; w < 8; w++) acc += s_cos[w];
        atomicAdd(&g_cos_sum, (double)acc);
    }
}

// Generic fallback for arbitrary D.
__global__ __launch_bounds__(256) void cos_kernel_generic(
    const float* __restrict__ emb,
    const void*  __restrict__ labels_raw,
    const float* __restrict__ protos,
    int B, int D, int C)
{
    const int warps_per_block = blockDim.x >> 5;
    const int warp = blockIdx.x * warps_per_block + (threadIdx.x >> 5);
    const int lane = threadIdx.x & 31;

    float dep = 0.f, dee = 0.f, dpp = 0.f;

    if (warp < B) {
        long long lab;
        if (g_is64) lab = ((const long long*)labels_raw)[warp];
        else        lab = (long long)((const int*)labels_raw)[warp];
        if (lab < 0) lab = 0;
        if (lab >= (long long)C) lab = C - 1;

        const float* e = emb + (size_t)warp * D;
        const float* p = protos + (size_t)lab * D;
        for (int i = lane; i < D; i += 32) {
            float ev = e[i], pv = p[i];
            dep = fmaf(ev, pv, dep);
            dee = fmaf(ev, ev, dee);
            dpp = fmaf(pv, pv, dpp);
        }
    }

    #pragma unroll
    for (int off = 16; off > 0; off >>= 1) {
        dep += __shfl_xor_sync(0xFFFFFFFFu, dep, off);
        dee += __shfl_xor_sync(0xFFFFFFFFu, dee, off);
        dpp += __shfl_xor_sync(0xFFFFFFFFu, dpp, off);
    }

    __shared__ float s_cos[8];
    if (lane == 0) {
        float cosv = 0.f;
        if (warp < B) {
            float en = fmaxf(sqrtf(dee), 1e-8f);
            float pn = fmaxf(sqrtf(dpp), 1e-8f);
            cosv = dep / (en * pn);
        }
        s_cos[threadIdx.x >> 5] = cosv;
    }
    __syncthreads();

    if (threadIdx.x == 0) {
        float acc = 0.f;
        #pragma unroll
        for (int w = 0; w < 8; w++) acc += s_cos[w];
        atomicAdd(&g_cos_sum, (double)acc);
    }
}

__global__ void finalize_kernel(float* out, int B) {
    out[0] = 1.0f - (float)(g_cos_sum / (double)B);
}

extern "C" void kernel_launch(void* const* d_in, const int* in_sizes, int n_in,
                              void* d_out, int out_size)
{
    // metadata order: embeddings [B*D] f32, labels [B] int, prototypes [C*D] f32
    const float* emb    = (const float*)d_in[0];
    const void*  labels = d_in[1];
    const float* protos = (const float*)d_in[2];
    float*       out    = (float*)d_out;

    const int B = in_sizes[1];
    const int D = in_sizes[0] / B;
    const int C = in_sizes[2] / D;

    init_kernel<<<1, 1>>>(labels, B, C);

    const int warps_per_block = 8;                 // 256 threads
    const int blocks = (B + warps_per_block - 1) / warps_per_block;

    if (D == 512) {
        cos_kernel_d512<<<blocks, 256>>>(emb, labels, protos, B, C);
    } else {
        cos_kernel_generic<<<blocks, 256>>>(emb, labels, protos, B, D, C);
    }

    finalize_kernel<<<1, 1>>>(out, B);
}